// round 3
// baseline (speedup 1.0000x reference)
#include <cuda_runtime.h>
#include <cstdint>

#define N_NODES 50000
#define N_EDGES 1600000
#define NODE_DIMV 3
#define EDGE_DIMV 32
#define HID 128
#define N_GRAPHS 512
#define N_HEADSV 5

typedef unsigned long long ull;

// ---------------- device scratch (no allocations allowed) ----------------
__device__ float g_h1[N_NODES * NODE_DIMV];          // conv1 output (pre node_proj)
__device__ float g_h2[N_NODES * HID];                // after node_proj (relu)
__device__ float g_acc2[N_NODES * HID];              // conv2 accumulator (init = h2)
__device__ float g_acc3[N_NODES * HID];              // conv3 accumulator (init = relu(acc2))
__device__ float g_Pd[N_NODES * 2 * HID];            // per-node dst projection: [f(128) | s(128)]
__device__ float g_Ps[N_NODES * 2 * HID];            // per-node src projection: [f(128) | s(128)]
__device__ float g_gsum[N_GRAPHS * HID];
__device__ float g_cnt[N_GRAPHS];

// ---------------- helpers ----------------
__device__ __forceinline__ float sigf(float v) {
    float z = __expf(-v);
    return __fdividef(1.0f, 1.0f + z);
}
__device__ __forceinline__ float spf(float v) {
    // softplus: max(v,0) + log1p(exp(-|v|))
    float a = fabsf(v);
    float t = __expf(-a);
    return fmaxf(v, 0.0f) + __logf(1.0f + t);
}
__device__ __forceinline__ ull pk2(float x, float y) {
    ull r; asm("mov.b64 %0, {%1,%2};" : "=l"(r) : "f"(x), "f"(y)); return r;
}
__device__ __forceinline__ void fma2(ull& d, ull a, ull b) {
    asm("fma.rn.f32x2 %0, %1, %2, %0;" : "+l"(d) : "l"(a), "l"(b));
}
__device__ __forceinline__ float2 upk2(ull v) {
    float2 r; asm("mov.b64 {%0,%1}, %2;" : "=f"(r.x), "=f"(r.y) : "l"(v)); return r;
}
__device__ __forceinline__ void red4(float* p, float a, float b, float c, float d) {
    asm volatile("red.global.add.v4.f32 [%0], {%1,%2,%3,%4};"
                 :: "l"(p), "f"(a), "f"(b), "f"(c), "f"(d) : "memory");
}

// ---------------- kernel 0: init h1 = x, zero pooling buffers ----------------
__global__ void k_init(const float* __restrict__ x) {
    int i = blockIdx.x * blockDim.x + threadIdx.x;
    if (i < N_NODES * NODE_DIMV) g_h1[i] = x[i];
    if (i < N_GRAPHS * HID) g_gsum[i] = 0.0f;
    if (i < N_GRAPHS) g_cnt[i] = 0.0f;
}

// ---------------- kernel 1: conv1 edges (channels=3, zdim=38) ----------------
__global__ void __launch_bounds__(256) k_conv1(
    const float* __restrict__ x, const float* __restrict__ ea,
    const int* __restrict__ src, const int* __restrict__ dst,
    const float* __restrict__ W1f, const float* __restrict__ b1f,
    const float* __restrict__ W1s, const float* __restrict__ b1s)
{
    __shared__ float swf[38 * 3], sws[38 * 3], sbf[3], sbs[3];
    int t = threadIdx.x;
    if (t < 114) { swf[t] = W1f[t]; sws[t] = W1s[t]; }
    if (t < 3)   { sbf[t] = b1f[t]; sbs[t] = b1s[t]; }
    __syncthreads();

    int e = blockIdx.x * blockDim.x + t;
    if (e >= N_EDGES) return;
    int s = src[e], d = dst[e];

    float xd[3], xs[3];
#pragma unroll
    for (int i = 0; i < 3; i++) { xd[i] = x[d * 3 + i]; xs[i] = x[s * 3 + i]; }

    float el[32];
    const float4* er = reinterpret_cast<const float4*>(ea + (size_t)e * 32);
#pragma unroll
    for (int q = 0; q < 8; q++) reinterpret_cast<float4*>(el)[q] = er[q];

#pragma unroll
    for (int c = 0; c < 3; c++) {
        float vf = sbf[c], vs = sbs[c];
#pragma unroll
        for (int i = 0; i < 3; i++) {
            vf += xd[i] * swf[i * 3 + c];        vs += xd[i] * sws[i * 3 + c];
            vf += xs[i] * swf[(3 + i) * 3 + c];  vs += xs[i] * sws[(3 + i) * 3 + c];
        }
#pragma unroll
        for (int k = 0; k < 32; k++) {
            vf += el[k] * swf[(6 + k) * 3 + c];
            vs += el[k] * sws[(6 + k) * 3 + c];
        }
        float m = sigf(vf) * spf(vs);
        atomicAdd(&g_h1[d * 3 + c], m);
    }
}

// ---------------- kernel 2: node projection h2 = relu(h1 @ Wp + bp) ----------------
__global__ void k_nodeproj(const float* __restrict__ Wp, const float* __restrict__ bp) {
    int i = blockIdx.x * blockDim.x + threadIdx.x;
    if (i >= N_NODES * HID) return;
    int n = i >> 7, c = i & 127;
    float a = g_h1[n * 3], b = g_h1[n * 3 + 1], d = g_h1[n * 3 + 2];
    float v = bp[c] + a * Wp[c] + b * Wp[128 + c] + d * Wp[256 + c];
    g_h2[i] = fmaxf(v, 0.0f);
}

// ---------------- kernel 3: 4-way node pre-projection GEMM ----------------
// mode 0: in = g_h2 (no relu), accout = g_acc2
// mode 1: in = relu(g_acc2),   accout = g_acc3
// Writes g_Pd[n][0:128]=in@Wf[0:128], g_Pd[n][128:256]=in@Ws[0:128],
//        g_Ps[n][0:128]=in@Wf[128:256], g_Ps[n][128:256]=in@Ws[128:256]
__global__ void __launch_bounds__(256) k_proj4(
    const float* __restrict__ Wf, const float* __restrict__ Ws, int mode)
{
    __shared__ __align__(16) float sA[64][128];
    __shared__ __align__(16) float sB[32][128];
    const float* in = (mode == 0) ? g_h2 : g_acc2;
    float* accout   = (mode == 0) ? g_acc2 : g_acc3;

    int t = threadIdx.x;
    int n0 = blockIdx.x * 64;

    for (int idx = t; idx < 64 * 128; idx += 256) {
        int r = idx >> 7, c = idx & 127;
        int n = n0 + r;
        float v = 0.0f;
        if (n < N_NODES) {
            v = in[(size_t)n * 128 + c];
            if (mode) v = fmaxf(v, 0.0f);
            accout[(size_t)n * 128 + c] = v;
        }
        sA[r][c] = v;
    }

    int cg = t & 31, ng = t >> 5;
    int c0 = cg * 4;

#pragma unroll
    for (int p = 0; p < 4; p++) {
        const float* W = (p == 0 || p == 2) ? Wf : Ws;
        int krow0 = (p < 2) ? 0 : 128;

        float4 acc[8];
#pragma unroll
        for (int j = 0; j < 8; j++) acc[j] = make_float4(0.f, 0.f, 0.f, 0.f);

        for (int kc = 0; kc < 4; kc++) {
            __syncthreads();
            for (int idx = t; idx < 32 * 128; idx += 256) {
                int r = idx >> 7, c = idx & 127;
                sB[r][c] = W[(size_t)(krow0 + kc * 32 + r) * 128 + c];
            }
            __syncthreads();
#pragma unroll
            for (int k = 0; k < 32; k++) {
                float4 b = *reinterpret_cast<const float4*>(&sB[k][c0]);
#pragma unroll
                for (int j = 0; j < 8; j++) {
                    float a = sA[ng + j * 8][kc * 32 + k];
                    acc[j].x += a * b.x; acc[j].y += a * b.y;
                    acc[j].z += a * b.z; acc[j].w += a * b.w;
                }
            }
        }
        float* out = (p < 2) ? g_Pd : g_Ps;
        int coff = (p == 0 || p == 2) ? 0 : 128;
#pragma unroll
        for (int j = 0; j < 8; j++) {
            int n = n0 + ng + j * 8;
            if (n < N_NODES)
                *reinterpret_cast<float4*>(&out[(size_t)n * 256 + coff + c0]) = acc[j];
        }
    }
}

// ---------------- kernel 4: fused edge kernel for conv2/conv3 ----------------
// Per edge: m = sigmoid(Pd_f[d] + Ps_f[s] + e@We_f + bf) * softplus(Pd_s[d] + Ps_s[s] + e@We_s + bs)
// red-add m into acc[d]. 4 edges per warp; edge-GEMM via packed f32x2 FMA.
__global__ void __launch_bounds__(256) k_conv_edges(
    const float* __restrict__ ea, const int* __restrict__ src, const int* __restrict__ dst,
    const float* __restrict__ We_f, const float* __restrict__ We_s,
    const float* __restrict__ bf, const float* __restrict__ bs, int mode)
{
    __shared__ __align__(16) float swf[32][128];
    __shared__ __align__(16) float sws[32][128];
    __shared__ __align__(16) float sbf[128];
    __shared__ __align__(16) float sbs[128];
    float* acc = (mode == 0) ? g_acc2 : g_acc3;

    int t = threadIdx.x;
    for (int idx = t; idx < 32 * 128; idx += 256) {
        swf[idx >> 7][idx & 127] = We_f[idx];
        sws[idx >> 7][idx & 127] = We_s[idx];
    }
    if (t < 128) { sbf[t] = bf[t]; sbs[t] = bs[t]; }
    __syncthreads();

    int warp = blockIdx.x * 8 + (t >> 5);
    int lane = t & 31;
    int e0 = warp * 4;
    if (e0 >= N_EDGES) return;

    int sj[4], dj[4];
    float eav[4];
#pragma unroll
    for (int j = 0; j < 4; j++) {
        sj[j] = src[e0 + j];
        dj[j] = dst[e0 + j];
        eav[j] = ea[(size_t)(e0 + j) * 32 + lane];
    }

    int c0 = lane * 4;
    ull accf[4][2], accs[4][2];
#pragma unroll
    for (int j = 0; j < 4; j++) {
        accf[j][0] = 0ull; accf[j][1] = 0ull;
        accs[j][0] = 0ull; accs[j][1] = 0ull;
    }

#pragma unroll
    for (int k = 0; k < 32; k++) {
        const ulonglong2 wf = *reinterpret_cast<const ulonglong2*>(&swf[k][c0]);
        const ulonglong2 ws = *reinterpret_cast<const ulonglong2*>(&sws[k][c0]);
#pragma unroll
        for (int j = 0; j < 4; j++) {
            float ek = __shfl_sync(0xffffffffu, eav[j], k);
            ull e2 = pk2(ek, ek);
            fma2(accf[j][0], wf.x, e2);
            fma2(accf[j][1], wf.y, e2);
            fma2(accs[j][0], ws.x, e2);
            fma2(accs[j][1], ws.y, e2);
        }
    }

    const float4 bfv = *reinterpret_cast<const float4*>(&sbf[c0]);
    const float4 bsv = *reinterpret_cast<const float4*>(&sbs[c0]);

#pragma unroll
    for (int j = 0; j < 4; j++) {
        int d = dj[j], s = sj[j];
        const float4 pdf = *reinterpret_cast<const float4*>(g_Pd + (size_t)d * 256 + c0);
        const float4 pds = *reinterpret_cast<const float4*>(g_Pd + (size_t)d * 256 + 128 + c0);
        const float4 psf = *reinterpret_cast<const float4*>(g_Ps + (size_t)s * 256 + c0);
        const float4 pss = *reinterpret_cast<const float4*>(g_Ps + (size_t)s * 256 + 128 + c0);

        float2 fa = upk2(accf[j][0]), fb = upk2(accf[j][1]);
        float2 sa = upk2(accs[j][0]), sb = upk2(accs[j][1]);

        float vf0 = fa.x + bfv.x + pdf.x + psf.x;
        float vf1 = fa.y + bfv.y + pdf.y + psf.y;
        float vf2 = fb.x + bfv.z + pdf.z + psf.z;
        float vf3 = fb.y + bfv.w + pdf.w + psf.w;
        float vs0 = sa.x + bsv.x + pds.x + pss.x;
        float vs1 = sa.y + bsv.y + pds.y + pss.y;
        float vs2 = sb.x + bsv.z + pds.z + pss.z;
        float vs3 = sb.y + bsv.w + pds.w + pss.w;

        float m0 = sigf(vf0) * spf(vs0);
        float m1 = sigf(vf1) * spf(vs1);
        float m2 = sigf(vf2) * spf(vs2);
        float m3 = sigf(vf3) * spf(vs3);

        red4(acc + (size_t)d * 128 + c0, m0, m1, m2, m3);
    }
}

// ---------------- kernel 5: pooling (relu + segment mean numerators) ----------------
__global__ void k_pool(const int* __restrict__ batch) {
    int i = blockIdx.x * blockDim.x + threadIdx.x;
    if (i >= N_NODES * 32) return;
    int n = i >> 5, q = i & 31;
    int b = batch[n];
    float4 v = *reinterpret_cast<const float4*>(&g_acc3[(size_t)n * 128 + q * 4]);
    v.x = fmaxf(v.x, 0.f); v.y = fmaxf(v.y, 0.f);
    v.z = fmaxf(v.z, 0.f); v.w = fmaxf(v.w, 0.f);
    red4(&g_gsum[(size_t)b * 128 + q * 4], v.x, v.y, v.z, v.w);
    if (q == 0) atomicAdd(&g_cnt[b], 1.0f);
}

// ---------------- kernel 6: head MLP ----------------
__global__ void __launch_bounds__(128) k_head(
    const float* __restrict__ Wfc, const float* __restrict__ bfc,
    const float* __restrict__ Wh, const float* __restrict__ bh,
    float* __restrict__ out)
{
    __shared__ float sg[128], sh[128];
    int b = blockIdx.x, t = threadIdx.x;
    float cnt = fmaxf(g_cnt[b], 1.0f);
    sg[t] = g_gsum[(size_t)b * 128 + t] / cnt;
    __syncthreads();
    float a = bfc[t];
#pragma unroll 8
    for (int k = 0; k < 128; k++) a += sg[k] * Wfc[k * 128 + t];
    sh[t] = fmaxf(a, 0.0f);
    __syncthreads();
    if (t < N_HEADSV) {
        float a2 = bh[t];
#pragma unroll 8
        for (int k = 0; k < 128; k++) a2 += sh[k] * Wh[k * 5 + t];
        out[b * 5 + t] = a2;
    }
}

// ---------------- launch ----------------
extern "C" void kernel_launch(void* const* d_in, const int* in_sizes, int n_in,
                              void* d_out, int out_size) {
    (void)in_sizes; (void)n_in; (void)out_size;
    const float* x    = (const float*)d_in[0];
    const float* ea   = (const float*)d_in[1];
    const int*   ei   = (const int*)d_in[2];
    const int*   batch= (const int*)d_in[3];
    const float* W1f  = (const float*)d_in[4];
    const float* b1f  = (const float*)d_in[5];
    const float* W1s  = (const float*)d_in[6];
    const float* b1s  = (const float*)d_in[7];
    const float* Wp   = (const float*)d_in[8];
    const float* bp   = (const float*)d_in[9];
    const float* W2f  = (const float*)d_in[10];
    const float* b2f  = (const float*)d_in[11];
    const float* W2s  = (const float*)d_in[12];
    const float* b2s  = (const float*)d_in[13];
    const float* W3f  = (const float*)d_in[14];
    const float* b3f  = (const float*)d_in[15];
    const float* W3s  = (const float*)d_in[16];
    const float* W3sb = (const float*)d_in[17];
    const float* Wfc  = (const float*)d_in[18];
    const float* bfc  = (const float*)d_in[19];
    const float* Wh   = (const float*)d_in[20];
    const float* bh   = (const float*)d_in[21];
    const int* src = ei;
    const int* dst = ei + N_EDGES;
    float* out = (float*)d_out;

    // 1) init h1 = x, zero pool buffers
    k_init<<<(N_NODES * NODE_DIMV + 255) / 256, 256>>>(x);
    // 2) conv1 (channels = 3)
    k_conv1<<<(N_EDGES + 255) / 256, 256>>>(x, ea, src, dst, W1f, b1f, W1s, b1s);
    // 3) node projection 3 -> 128 with relu
    k_nodeproj<<<(N_NODES * HID + 255) / 256, 256>>>(Wp, bp);
    // 4) conv2: pre-project nodes, then fused edge pass
    k_proj4<<<(N_NODES + 63) / 64, 256>>>(W2f, W2s, 0);
    k_conv_edges<<<N_EDGES / 32, 256>>>(ea, src, dst,
                                        W2f + 256 * 128, W2s + 256 * 128, b2f, b2s, 0);
    // 5) conv3: relu(acc2) -> pre-project, fused edge pass
    k_proj4<<<(N_NODES + 63) / 64, 256>>>(W3f, W3s, 1);
    k_conv_edges<<<N_EDGES / 32, 256>>>(ea, src, dst,
                                        W3f + 256 * 128, W3s + 256 * 128, b3f, W3sb, 1);
    // 6) pooling
    k_pool<<<(N_NODES * 32 + 255) / 256, 256>>>(batch);
    // 7) head MLP
    k_head<<<N_GRAPHS, 128>>>(Wfc, bfc, Wh, bh, out);
}

// round 4
// speedup vs baseline: 1.1503x; 1.1503x over previous
#include <cuda_runtime.h>
#include <cuda_fp16.h>
#include <cstdint>

#define N_NODES 50000
#define N_EDGES 1600000
#define NODE_DIMV 3
#define HID 128
#define N_GRAPHS 512
#define N_HEADSV 5

// ---------------- device scratch ----------------
__device__ float  g_h1[N_NODES * NODE_DIMV];      // conv1 output
__device__ float  g_acc2[N_NODES * HID];          // conv2 accumulator (init = h2)
__device__ float  g_acc3[N_NODES * HID];          // conv3 accumulator (init = relu(acc2))
__device__ __half g_P[N_NODES * 512];             // node proj table: [fd|sd|fs|ss] per node
__device__ __half g_Pe[(size_t)N_EDGES * 256];    // edge proj: [f128|s128] per edge (reused conv2/conv3)
__device__ float  g_gsum[N_GRAPHS * HID];
__device__ float  g_cnt[N_GRAPHS];

// ---------------- helpers ----------------
__device__ __forceinline__ float sigf(float v) {
    float z = __expf(-v);
    return __fdividef(1.0f, 1.0f + z);
}
__device__ __forceinline__ float spf(float v) {
    float a = fabsf(v);
    float t = __expf(-a);
    return fmaxf(v, 0.0f) + __logf(1.0f + t);
}
__device__ __forceinline__ void red4(float* p, float a, float b, float c, float d) {
    asm volatile("red.global.add.v4.f32 [%0], {%1,%2,%3,%4};"
                 :: "l"(p), "f"(a), "f"(b), "f"(c), "f"(d) : "memory");
}
__device__ __forceinline__ uint32_t to_tf32(float v) {
    uint32_t r; asm("cvt.rna.tf32.f32 %0, %1;" : "=r"(r) : "f"(v)); return r;
}
__device__ __forceinline__ void mma_tf32(float c[4], const uint32_t a[4], const uint32_t b[2]) {
    asm volatile(
        "mma.sync.aligned.m16n8k8.row.col.f32.tf32.tf32.f32 "
        "{%0,%1,%2,%3},{%4,%5,%6,%7},{%8,%9},{%0,%1,%2,%3};"
        : "+f"(c[0]), "+f"(c[1]), "+f"(c[2]), "+f"(c[3])
        : "r"(a[0]), "r"(a[1]), "r"(a[2]), "r"(a[3]), "r"(b[0]), "r"(b[1]));
}
__device__ __forceinline__ float4 ldh4(const __half* p) {
    uint2 u = *reinterpret_cast<const uint2*>(p);
    __half2 a = *reinterpret_cast<__half2*>(&u.x);
    __half2 b = *reinterpret_cast<__half2*>(&u.y);
    float2 x = __half22float2(a), y = __half22float2(b);
    return make_float4(x.x, x.y, y.x, y.y);
}

// ---------------- kernel 0: init ----------------
__global__ void k_init(const float* __restrict__ x) {
    int i = blockIdx.x * blockDim.x + threadIdx.x;
    if (i < N_NODES * NODE_DIMV) g_h1[i] = x[i];
    if (i < N_GRAPHS * HID) g_gsum[i] = 0.0f;
    if (i < N_GRAPHS) g_cnt[i] = 0.0f;
}

// ---------------- kernel 1: conv1 edges (channels=3, zdim=38) ----------------
__global__ void __launch_bounds__(256) k_conv1(
    const float* __restrict__ x, const float* __restrict__ ea,
    const int* __restrict__ src, const int* __restrict__ dst,
    const float* __restrict__ W1f, const float* __restrict__ b1f,
    const float* __restrict__ W1s, const float* __restrict__ b1s)
{
    __shared__ float swf[38 * 3], sws[38 * 3], sbf[3], sbs[3];
    int t = threadIdx.x;
    if (t < 114) { swf[t] = W1f[t]; sws[t] = W1s[t]; }
    if (t < 3)   { sbf[t] = b1f[t]; sbs[t] = b1s[t]; }
    __syncthreads();

    int e = blockIdx.x * blockDim.x + t;
    if (e >= N_EDGES) return;
    int s = src[e], d = dst[e];

    float xd[3], xs[3];
#pragma unroll
    for (int i = 0; i < 3; i++) { xd[i] = x[d * 3 + i]; xs[i] = x[s * 3 + i]; }

    float el[32];
    const float4* er = reinterpret_cast<const float4*>(ea + (size_t)e * 32);
#pragma unroll
    for (int q = 0; q < 8; q++) reinterpret_cast<float4*>(el)[q] = er[q];

#pragma unroll
    for (int c = 0; c < 3; c++) {
        float vf = sbf[c], vs = sbs[c];
#pragma unroll
        for (int i = 0; i < 3; i++) {
            vf += xd[i] * swf[i * 3 + c];        vs += xd[i] * sws[i * 3 + c];
            vf += xs[i] * swf[(3 + i) * 3 + c];  vs += xs[i] * sws[(3 + i) * 3 + c];
        }
#pragma unroll
        for (int k = 0; k < 32; k++) {
            vf += el[k] * swf[(6 + k) * 3 + c];
            vs += el[k] * sws[(6 + k) * 3 + c];
        }
        float m = sigf(vf) * spf(vs);
        atomicAdd(&g_h1[d * 3 + c], m);
    }
}

// ---------------- kernel 2: node projection -> g_acc2 = relu(h1 @ Wp + bp) ----------------
__global__ void k_nodeproj(const float* __restrict__ Wp, const float* __restrict__ bp) {
    int i = blockIdx.x * blockDim.x + threadIdx.x;
    if (i >= N_NODES * HID) return;
    int n = i >> 7, c = i & 127;
    float a = g_h1[n * 3], b = g_h1[n * 3 + 1], d = g_h1[n * 3 + 2];
    float v = bp[c] + a * Wp[c] + b * Wp[128 + c] + d * Wp[256 + c];
    g_acc2[i] = fmaxf(v, 0.0f);
}

// ---------------- kernel: acc3 = relu(acc2) ----------------
__global__ void k_prep() {
    int i = blockIdx.x * blockDim.x + threadIdx.x;
    if (i < N_NODES * HID) g_acc3[i] = fmaxf(g_acc2[i], 0.0f);
}

// ---------------- tf32 tensor-core GEMM ----------------
// D[M x (128*gridDim.y)] = A[M x (32*kchunks)] @ W[(32*kchunks) x 128-per-n-block], fp16 out.
// blockIdx.y selects which 128-col slab: W = (bn&1)? Ws : Wf, krow0 = (bn>>1)*128.
// amode: 0 -> g_acc2, 1 -> g_acc3, 2 -> Aext.  pout: 0 -> g_P, 1 -> g_Pe.
__global__ void __launch_bounds__(256) k_gemm(
    const float* __restrict__ Aext, int lda, int M, int kchunks,
    const float* __restrict__ Wf, const float* __restrict__ Ws,
    int amode, int pout)
{
    __shared__ uint32_t As[128][32];
    __shared__ uint32_t Bs[128][32];

    const float* A = (amode == 0) ? g_acc2 : (amode == 1) ? g_acc3 : Aext;
    __half* P = pout ? g_Pe : g_P;
    int ldP = 128 * gridDim.y;

    int t = threadIdx.x;
    int m0 = blockIdx.x * 128;
    int bn = blockIdx.y;
    const float* W = (bn & 1) ? Ws : Wf;
    int krow0 = (bn >> 1) * 128;

    int lane = t & 31, warp = t >> 5;
    int gid = lane >> 2, tig = lane & 3;
    int wm = warp >> 1, wn = warp & 1;

    float c[2][8][4] = {};

    for (int kc = 0; kc < kchunks; kc++) {
        // stage A chunk [128 x 32], swizzled
#pragma unroll
        for (int i = 0; i < 16; i++) {
            int idx = t + i * 256;
            int m = idx >> 5, k = idx & 31;
            int row = m0 + m;
            float v = (row < M) ? A[(size_t)row * lda + kc * 32 + k] : 0.0f;
            As[m][k ^ ((m & 7) << 2)] = to_tf32(v);
        }
        // stage B chunk: Bs[n][k] = W[(krow0+kc*32+k)*128 + n]
#pragma unroll
        for (int i = 0; i < 16; i++) {
            int idx = t + i * 256;
            int k = idx >> 7, n = idx & 127;
            float v = W[(size_t)(krow0 + kc * 32 + k) * HID + n];
            Bs[n][k ^ ((n & 7) << 2)] = to_tf32(v);
        }
        __syncthreads();

#pragma unroll
        for (int ks = 0; ks < 4; ks++) {
            int k0 = ks * 8;
            uint32_t a[2][4];
#pragma unroll
            for (int mt = 0; mt < 2; mt++) {
                int m = wm * 32 + mt * 16 + gid;
                int sw = (m & 7) << 2;
                a[mt][0] = As[m][(k0 + tig) ^ sw];
                a[mt][1] = As[m + 8][(k0 + tig) ^ sw];
                a[mt][2] = As[m][(k0 + tig + 4) ^ sw];
                a[mt][3] = As[m + 8][(k0 + tig + 4) ^ sw];
            }
#pragma unroll
            for (int nt = 0; nt < 8; nt++) {
                int n = wn * 64 + nt * 8 + gid;
                int sw = (n & 7) << 2;
                uint32_t b[2] = { Bs[n][(k0 + tig) ^ sw], Bs[n][(k0 + tig + 4) ^ sw] };
                mma_tf32(c[0][nt], a[0], b);
                mma_tf32(c[1][nt], a[1], b);
            }
        }
        __syncthreads();
    }

    // epilogue: fp16 store
    int rb = m0 + wm * 32;
#pragma unroll
    for (int mt = 0; mt < 2; mt++) {
#pragma unroll
        for (int nt = 0; nt < 8; nt++) {
            int r0 = rb + mt * 16 + gid;
            int cc = bn * 128 + wn * 64 + nt * 8 + 2 * tig;
            if (r0 < M)
                *reinterpret_cast<__half2*>(P + (size_t)r0 * ldP + cc) =
                    __floats2half2_rn(c[mt][nt][0], c[mt][nt][1]);
            int r1 = r0 + 8;
            if (r1 < M)
                *reinterpret_cast<__half2*>(P + (size_t)r1 * ldP + cc) =
                    __floats2half2_rn(c[mt][nt][2], c[mt][nt][3]);
        }
    }
}

// ---------------- edge kernel: gather + activation + scatter only ----------------
__global__ void __launch_bounds__(256) k_edge(
    const int* __restrict__ src, const int* __restrict__ dst,
    const float* __restrict__ bf, const float* __restrict__ bs, int mode)
{
    __shared__ float sbf[128], sbs[128];
    int t = threadIdx.x;
    if (t < 128) sbf[t] = bf[t]; else sbs[t - 128] = bs[t - 128];
    __syncthreads();

    float* acc = (mode == 0) ? g_acc2 : g_acc3;
    int warp = blockIdx.x * 8 + (t >> 5);
    int lane = t & 31;
    int e0 = warp * 4;
    int c0 = lane * 4;

    const float4 bfv = *reinterpret_cast<const float4*>(&sbf[c0]);
    const float4 bsv = *reinterpret_cast<const float4*>(&sbs[c0]);

#pragma unroll
    for (int j = 0; j < 4; j++) {
        int e = e0 + j;
        int d = dst[e], s = src[e];
        const __half* pe = g_Pe + (size_t)e * 256;
        const __half* pd = g_P + (size_t)d * 512;
        const __half* ps = g_P + (size_t)s * 512;

        float4 ef = ldh4(pe + c0);
        float4 es = ldh4(pe + 128 + c0);
        float4 fd = ldh4(pd + c0);          // dst, f-part
        float4 sd = ldh4(pd + 128 + c0);    // dst, s-part
        float4 fs = ldh4(ps + 256 + c0);    // src, f-part
        float4 ss = ldh4(ps + 384 + c0);    // src, s-part

        float vf0 = ef.x + fd.x + fs.x + bfv.x;
        float vf1 = ef.y + fd.y + fs.y + bfv.y;
        float vf2 = ef.z + fd.z + fs.z + bfv.z;
        float vf3 = ef.w + fd.w + fs.w + bfv.w;
        float vs0 = es.x + sd.x + ss.x + bsv.x;
        float vs1 = es.y + sd.y + ss.y + bsv.y;
        float vs2 = es.z + sd.z + ss.z + bsv.z;
        float vs3 = es.w + sd.w + ss.w + bsv.w;

        float m0 = sigf(vf0) * spf(vs0);
        float m1 = sigf(vf1) * spf(vs1);
        float m2 = sigf(vf2) * spf(vs2);
        float m3 = sigf(vf3) * spf(vs3);

        red4(acc + (size_t)d * 128 + c0, m0, m1, m2, m3);
    }
}

// ---------------- pooling ----------------
__global__ void k_pool(const int* __restrict__ batch) {
    int i = blockIdx.x * blockDim.x + threadIdx.x;
    if (i >= N_NODES * 32) return;
    int n = i >> 5, q = i & 31;
    int b = batch[n];
    float4 v = *reinterpret_cast<const float4*>(&g_acc3[(size_t)n * 128 + q * 4]);
    v.x = fmaxf(v.x, 0.f); v.y = fmaxf(v.y, 0.f);
    v.z = fmaxf(v.z, 0.f); v.w = fmaxf(v.w, 0.f);
    red4(&g_gsum[(size_t)b * 128 + q * 4], v.x, v.y, v.z, v.w);
    if (q == 0) atomicAdd(&g_cnt[b], 1.0f);
}

// ---------------- head MLP ----------------
__global__ void __launch_bounds__(128) k_head(
    const float* __restrict__ Wfc, const float* __restrict__ bfc,
    const float* __restrict__ Wh, const float* __restrict__ bh,
    float* __restrict__ out)
{
    __shared__ float sg[128], sh[128];
    int b = blockIdx.x, t = threadIdx.x;
    float cnt = fmaxf(g_cnt[b], 1.0f);
    sg[t] = g_gsum[(size_t)b * 128 + t] / cnt;
    __syncthreads();
    float a = bfc[t];
#pragma unroll 8
    for (int k = 0; k < 128; k++) a += sg[k] * Wfc[k * 128 + t];
    sh[t] = fmaxf(a, 0.0f);
    __syncthreads();
    if (t < N_HEADSV) {
        float a2 = bh[t];
#pragma unroll 8
        for (int k = 0; k < 128; k++) a2 += sh[k] * Wh[k * 5 + t];
        out[b * 5 + t] = a2;
    }
}

// ---------------- launch ----------------
extern "C" void kernel_launch(void* const* d_in, const int* in_sizes, int n_in,
                              void* d_out, int out_size) {
    (void)in_sizes; (void)n_in; (void)out_size;
    const float* x    = (const float*)d_in[0];
    const float* ea   = (const float*)d_in[1];
    const int*   ei   = (const int*)d_in[2];
    const int*   batch= (const int*)d_in[3];
    const float* W1f  = (const float*)d_in[4];
    const float* b1f  = (const float*)d_in[5];
    const float* W1s  = (const float*)d_in[6];
    const float* b1s  = (const float*)d_in[7];
    const float* Wp   = (const float*)d_in[8];
    const float* bp   = (const float*)d_in[9];
    const float* W2f  = (const float*)d_in[10];
    const float* b2f  = (const float*)d_in[11];
    const float* W2s  = (const float*)d_in[12];
    const float* b2s  = (const float*)d_in[13];
    const float* W3f  = (const float*)d_in[14];
    const float* b3f  = (const float*)d_in[15];
    const float* W3s  = (const float*)d_in[16];
    const float* b3s  = (const float*)d_in[17];
    const float* Wfc  = (const float*)d_in[18];
    const float* bfc  = (const float*)d_in[19];
    const float* Wh   = (const float*)d_in[20];
    const float* bh   = (const float*)d_in[21];
    const int* src = ei;
    const int* dst = ei + N_EDGES;
    float* out = (float*)d_out;

    // 1) init
    k_init<<<(N_NODES * HID + 255) / 256, 256>>>(x);
    // 2) conv1 (channels = 3)
    k_conv1<<<(N_EDGES + 255) / 256, 256>>>(x, ea, src, dst, W1f, b1f, W1s, b1s);
    // 3) node projection 3 -> 128 with relu  => g_acc2 (== h2)
    k_nodeproj<<<(N_NODES * HID + 255) / 256, 256>>>(Wp, bp);

    // 4) conv2: node proj table (tf32 mma), edge proj table (tf32 mma), edge pass
    k_gemm<<<dim3(391, 4), 256>>>(nullptr, HID, N_NODES, 4, W2f, W2s, 0, 0);
    k_gemm<<<dim3(N_EDGES / 128, 2), 256>>>(ea, 32, N_EDGES, 1,
                                            W2f + 256 * 128, W2s + 256 * 128, 2, 1);
    k_edge<<<N_EDGES / 32, 256>>>(src, dst, b2f, b2s, 0);   // launch #6: profiled

    // 5) conv3
    k_prep<<<(N_NODES * HID + 255) / 256, 256>>>();
    k_gemm<<<dim3(391, 4), 256>>>(nullptr, HID, N_NODES, 4, W3f, W3s, 1, 0);
    k_gemm<<<dim3(N_EDGES / 128, 2), 256>>>(ea, 32, N_EDGES, 1,
                                            W3f + 256 * 128, W3s + 256 * 128, 2, 1);
    k_edge<<<N_EDGES / 32, 256>>>(src, dst, b3f, b3s, 1);

    // 6) pooling + head
    k_pool<<<(N_NODES * 32 + 255) / 256, 256>>>(batch);
    k_head<<<N_GRAPHS, 128>>>(Wfc, bfc, Wh, bh, out);
}

// round 5
// speedup vs baseline: 1.5017x; 1.3056x over previous
#include <cuda_runtime.h>
#include <cuda_fp16.h>
#include <cstdint>

#define N_NODES 50000
#define N_EDGES 1600000
#define NODE_DIMV 3
#define HID 128
#define N_GRAPHS 512
#define N_HEADSV 5

// ---------------- device scratch ----------------
__device__ float  g_h1[N_NODES * NODE_DIMV];      // conv1 output
__device__ float  g_acc2[N_NODES * HID];          // conv2 accumulator (init = h2)
__device__ float  g_acc3[N_NODES * HID];          // conv3 accumulator (init = relu(acc2))
__device__ __half g_P[N_NODES * 512];             // node proj table: [fd|sd|fs|ss] per node
__device__ float  g_gsum[N_GRAPHS * HID];
__device__ float  g_cnt[N_GRAPHS];

// ---------------- helpers ----------------
__device__ __forceinline__ float sigf(float v) {
    float z = __expf(-v);
    return __fdividef(1.0f, 1.0f + z);
}
__device__ __forceinline__ float spf(float v) {
    float a = fabsf(v);
    float t = __expf(-a);
    return fmaxf(v, 0.0f) + __logf(1.0f + t);
}
__device__ __forceinline__ void red4(float* p, float a, float b, float c, float d) {
    asm volatile("red.global.add.v4.f32 [%0], {%1,%2,%3,%4};"
                 :: "l"(p), "f"(a), "f"(b), "f"(c), "f"(d) : "memory");
}
__device__ __forceinline__ uint32_t to_tf32(float v) {
    uint32_t r; asm("cvt.rna.tf32.f32 %0, %1;" : "=r"(r) : "f"(v)); return r;
}
__device__ __forceinline__ void mma_tf32(float c[4], const uint32_t a[4], const uint32_t b[2]) {
    asm volatile(
        "mma.sync.aligned.m16n8k8.row.col.f32.tf32.tf32.f32 "
        "{%0,%1,%2,%3},{%4,%5,%6,%7},{%8,%9},{%0,%1,%2,%3};"
        : "+f"(c[0]), "+f"(c[1]), "+f"(c[2]), "+f"(c[3])
        : "r"(a[0]), "r"(a[1]), "r"(a[2]), "r"(a[3]), "r"(b[0]), "r"(b[1]));
}
__device__ __forceinline__ float4 ldh4(const __half* p) {
    uint2 u = *reinterpret_cast<const uint2*>(p);
    __half2 a = *reinterpret_cast<__half2*>(&u.x);
    __half2 b = *reinterpret_cast<__half2*>(&u.y);
    float2 x = __half22float2(a), y = __half22float2(b);
    return make_float4(x.x, x.y, y.x, y.y);
}

// ---------------- kernel 0: init ----------------
__global__ void k_init(const float* __restrict__ x) {
    int i = blockIdx.x * blockDim.x + threadIdx.x;
    if (i < N_NODES * NODE_DIMV) g_h1[i] = x[i];
    if (i < N_GRAPHS * HID) g_gsum[i] = 0.0f;
    if (i < N_GRAPHS) g_cnt[i] = 0.0f;
}

// ---------------- kernel 1: conv1 edges (channels=3, zdim=38) ----------------
__global__ void __launch_bounds__(256) k_conv1(
    const float* __restrict__ x, const float* __restrict__ ea,
    const int* __restrict__ src, const int* __restrict__ dst,
    const float* __restrict__ W1f, const float* __restrict__ b1f,
    const float* __restrict__ W1s, const float* __restrict__ b1s)
{
    __shared__ float swf[38 * 3], sws[38 * 3], sbf[3], sbs[3];
    int t = threadIdx.x;
    if (t < 114) { swf[t] = W1f[t]; sws[t] = W1s[t]; }
    if (t < 3)   { sbf[t] = b1f[t]; sbs[t] = b1s[t]; }
    __syncthreads();

    int e = blockIdx.x * blockDim.x + t;
    if (e >= N_EDGES) return;
    int s = src[e], d = dst[e];

    float xd[3], xs[3];
#pragma unroll
    for (int i = 0; i < 3; i++) { xd[i] = x[d * 3 + i]; xs[i] = x[s * 3 + i]; }

    float el[32];
    const float4* er = reinterpret_cast<const float4*>(ea + (size_t)e * 32);
#pragma unroll
    for (int q = 0; q < 8; q++) reinterpret_cast<float4*>(el)[q] = er[q];

#pragma unroll
    for (int c = 0; c < 3; c++) {
        float vf = sbf[c], vs = sbs[c];
#pragma unroll
        for (int i = 0; i < 3; i++) {
            vf += xd[i] * swf[i * 3 + c];        vs += xd[i] * sws[i * 3 + c];
            vf += xs[i] * swf[(3 + i) * 3 + c];  vs += xs[i] * sws[(3 + i) * 3 + c];
        }
#pragma unroll
        for (int k = 0; k < 32; k++) {
            vf += el[k] * swf[(6 + k) * 3 + c];
            vs += el[k] * sws[(6 + k) * 3 + c];
        }
        float m = sigf(vf) * spf(vs);
        atomicAdd(&g_h1[d * 3 + c], m);
    }
}

// ---------------- kernel 2: node projection -> g_acc2 = relu(h1 @ Wp + bp) ----------------
__global__ void k_nodeproj(const float* __restrict__ Wp, const float* __restrict__ bp) {
    int i = blockIdx.x * blockDim.x + threadIdx.x;
    if (i >= N_NODES * HID) return;
    int n = i >> 7, c = i & 127;
    float a = g_h1[n * 3], b = g_h1[n * 3 + 1], d = g_h1[n * 3 + 2];
    float v = bp[c] + a * Wp[c] + b * Wp[128 + c] + d * Wp[256 + c];
    g_acc2[i] = fmaxf(v, 0.0f);
}

// ---------------- node pre-projection GEMM (tf32 mma) -> g_P (fp16) ----------------
// grid (ceil(N/128), 4). slab bn: W = (bn&1)?Ws:Wf, krow0 = (bn>>1)*128, out cols bn*128.
// relu_mode 0: A = g_acc2 as-is (conv2). relu_mode 1: A = relu(g_acc2), and the
// bn==0 blocks also write g_acc3 = relu(g_acc2) (conv3 accumulator init).
__global__ void __launch_bounds__(256) k_gemm_node(
    const float* __restrict__ Wf, const float* __restrict__ Ws, int relu_mode)
{
    __shared__ uint32_t As[128][32];
    __shared__ uint32_t Bs[128][32];

    int t = threadIdx.x;
    int m0 = blockIdx.x * 128;
    int bn = blockIdx.y;
    const float* W = (bn & 1) ? Ws : Wf;
    int krow0 = (bn >> 1) * 128;

    int lane = t & 31, warp = t >> 5;
    int gid = lane >> 2, tig = lane & 3;
    int wm = warp >> 1, wn = warp & 1;

    float c[2][8][4] = {};

    for (int kc = 0; kc < 4; kc++) {
#pragma unroll
        for (int i = 0; i < 16; i++) {
            int idx = t + i * 256;
            int m = idx >> 5, k = idx & 31;
            int row = m0 + m;
            float v = 0.0f;
            if (row < N_NODES) {
                v = g_acc2[(size_t)row * HID + kc * 32 + k];
                if (relu_mode) {
                    v = fmaxf(v, 0.0f);
                    if (bn == 0) g_acc3[(size_t)row * HID + kc * 32 + k] = v;
                }
            }
            As[m][k ^ ((m & 7) << 2)] = to_tf32(v);
        }
#pragma unroll
        for (int i = 0; i < 16; i++) {
            int idx = t + i * 256;
            int k = idx >> 7, n = idx & 127;
            float v = W[(size_t)(krow0 + kc * 32 + k) * HID + n];
            Bs[n][k ^ ((n & 7) << 2)] = to_tf32(v);
        }
        __syncthreads();

#pragma unroll
        for (int ks = 0; ks < 4; ks++) {
            int k0 = ks * 8;
            uint32_t a[2][4];
#pragma unroll
            for (int mt = 0; mt < 2; mt++) {
                int m = wm * 32 + mt * 16 + gid;
                int sw = (m & 7) << 2;
                a[mt][0] = As[m][(k0 + tig) ^ sw];
                a[mt][1] = As[m + 8][(k0 + tig) ^ sw];
                a[mt][2] = As[m][(k0 + tig + 4) ^ sw];
                a[mt][3] = As[m + 8][(k0 + tig + 4) ^ sw];
            }
#pragma unroll
            for (int nt = 0; nt < 8; nt++) {
                int n = wn * 64 + nt * 8 + gid;
                int sw = (n & 7) << 2;
                uint32_t b[2] = { Bs[n][(k0 + tig) ^ sw], Bs[n][(k0 + tig + 4) ^ sw] };
                mma_tf32(c[0][nt], a[0], b);
                mma_tf32(c[1][nt], a[1], b);
            }
        }
        __syncthreads();
    }

    int rb = m0 + wm * 32;
#pragma unroll
    for (int mt = 0; mt < 2; mt++) {
#pragma unroll
        for (int nt = 0; nt < 8; nt++) {
            int r0 = rb + mt * 16 + gid;
            int cc = bn * 128 + wn * 64 + nt * 8 + 2 * tig;
            if (r0 < N_NODES)
                *reinterpret_cast<__half2*>(g_P + (size_t)r0 * 512 + cc) =
                    __floats2half2_rn(c[mt][nt][0], c[mt][nt][1]);
            int r1 = r0 + 8;
            if (r1 < N_NODES)
                *reinterpret_cast<__half2*>(g_P + (size_t)r1 * 512 + cc) =
                    __floats2half2_rn(c[mt][nt][2], c[mt][nt][3]);
        }
    }
}

// ---------------- fused conv edge kernel ----------------
// One block = 64 edges. tf32 mma computes ea[64x32] @ [We_f|We_s][32x256] into an
// fp16 smem tile (aliasing the staging smem), then per-warp gather/activate/scatter.
__global__ void __launch_bounds__(256) k_fused(
    const float* __restrict__ ea, const int* __restrict__ src, const int* __restrict__ dst,
    const float* __restrict__ Wef, const float* __restrict__ Wes,
    const float* __restrict__ bf, const float* __restrict__ bs, int mode)
{
    __shared__ union {
        struct { uint32_t As[64][32]; uint32_t Bs[256][32]; } st;
        __half m[64][264];
    } u;
    __shared__ float sbf[128], sbs[128];
    __shared__ int sdst[64], ssrc[64];

    float* acc = (mode == 0) ? g_acc2 : g_acc3;
    int t = threadIdx.x;
    int e0 = blockIdx.x * 64;

    if (t < 128) sbf[t] = bf[t];
    else         sbs[t - 128] = bs[t - 128];
    if (t < 64)       sdst[t] = dst[e0 + t];
    else if (t < 128) ssrc[t - 64] = src[e0 + t - 64];

    // stage A: edge attrs [64 x 32]
#pragma unroll
    for (int i = 0; i < 8; i++) {
        int idx = t + i * 256;
        int r = idx >> 5, k = idx & 31;
        u.st.As[r][k ^ ((r & 7) << 2)] = to_tf32(ea[(size_t)(e0 + r) * 32 + k]);
    }
    // stage B: weights [256 x 32] (cols 0-127 = f, 128-255 = s)
#pragma unroll
    for (int i = 0; i < 32; i++) {
        int idx = t + i * 256;
        int k = idx >> 8, n = idx & 255;
        float v = (n < 128) ? Wef[k * 128 + n] : Wes[k * 128 + (n - 128)];
        u.st.Bs[n][k ^ ((n & 7) << 2)] = to_tf32(v);
    }
    __syncthreads();

    int lane = t & 31, warp = t >> 5;
    int gid = lane >> 2, tig = lane & 3;
    int wm = warp >> 2, wn = warp & 3;   // wm: 2x32 rows, wn: 4x64 cols

    float c[2][8][4] = {};
#pragma unroll
    for (int ks = 0; ks < 4; ks++) {
        int k0 = ks * 8;
        uint32_t a[2][4];
#pragma unroll
        for (int mt = 0; mt < 2; mt++) {
            int m = wm * 32 + mt * 16 + gid;
            int sw = (m & 7) << 2;
            a[mt][0] = u.st.As[m][(k0 + tig) ^ sw];
            a[mt][1] = u.st.As[m + 8][(k0 + tig) ^ sw];
            a[mt][2] = u.st.As[m][(k0 + tig + 4) ^ sw];
            a[mt][3] = u.st.As[m + 8][(k0 + tig + 4) ^ sw];
        }
#pragma unroll
        for (int nt = 0; nt < 8; nt++) {
            int n = wn * 64 + nt * 8 + gid;
            int sw = (n & 7) << 2;
            uint32_t b[2] = { u.st.Bs[n][(k0 + tig) ^ sw], u.st.Bs[n][(k0 + tig + 4) ^ sw] };
            mma_tf32(c[0][nt], a[0], b);
            mma_tf32(c[1][nt], a[1], b);
        }
    }
    __syncthreads();   // all mma reads of staging done before aliasing overwrite

    // write raw edge-proj m-tile as fp16 (padded 264 cols for bank spread)
#pragma unroll
    for (int mt = 0; mt < 2; mt++) {
#pragma unroll
        for (int nt = 0; nt < 8; nt++) {
            int r = wm * 32 + mt * 16 + gid;
            int cc = wn * 64 + nt * 8 + 2 * tig;
            *reinterpret_cast<__half2*>(&u.m[r][cc]) =
                __floats2half2_rn(c[mt][nt][0], c[mt][nt][1]);
            *reinterpret_cast<__half2*>(&u.m[r + 8][cc]) =
                __floats2half2_rn(c[mt][nt][2], c[mt][nt][3]);
        }
    }
    __syncthreads();

    // edge phase: 8 edges per warp — gather node proj, activation, scatter
    int c0 = lane * 4;
    const float4 bfv = *reinterpret_cast<const float4*>(&sbf[c0]);
    const float4 bsv = *reinterpret_cast<const float4*>(&sbs[c0]);

#pragma unroll
    for (int j = 0; j < 8; j++) {
        int el = warp * 8 + j;
        int d = sdst[el], s = ssrc[el];
        const __half* pd = g_P + (size_t)d * 512;
        const __half* ps = g_P + (size_t)s * 512;

        float4 ef = ldh4(&u.m[el][c0]);
        float4 es = ldh4(&u.m[el][128 + c0]);
        float4 fd = ldh4(pd + c0);          // dst, f-part
        float4 sd = ldh4(pd + 128 + c0);    // dst, s-part
        float4 fs = ldh4(ps + 256 + c0);    // src, f-part
        float4 ss = ldh4(ps + 384 + c0);    // src, s-part

        float vf0 = ef.x + fd.x + fs.x + bfv.x;
        float vf1 = ef.y + fd.y + fs.y + bfv.y;
        float vf2 = ef.z + fd.z + fs.z + bfv.z;
        float vf3 = ef.w + fd.w + fs.w + bfv.w;
        float vs0 = es.x + sd.x + ss.x + bsv.x;
        float vs1 = es.y + sd.y + ss.y + bsv.y;
        float vs2 = es.z + sd.z + ss.z + bsv.z;
        float vs3 = es.w + sd.w + ss.w + bsv.w;

        float m0 = sigf(vf0) * spf(vs0);
        float m1 = sigf(vf1) * spf(vs1);
        float m2 = sigf(vf2) * spf(vs2);
        float m3 = sigf(vf3) * spf(vs3);

        red4(acc + (size_t)d * 128 + c0, m0, m1, m2, m3);
    }
}

// ---------------- pooling ----------------
__global__ void k_pool(const int* __restrict__ batch) {
    int i = blockIdx.x * blockDim.x + threadIdx.x;
    if (i >= N_NODES * 32) return;
    int n = i >> 5, q = i & 31;
    int b = batch[n];
    float4 v = *reinterpret_cast<const float4*>(&g_acc3[(size_t)n * 128 + q * 4]);
    v.x = fmaxf(v.x, 0.f); v.y = fmaxf(v.y, 0.f);
    v.z = fmaxf(v.z, 0.f); v.w = fmaxf(v.w, 0.f);
    red4(&g_gsum[(size_t)b * 128 + q * 4], v.x, v.y, v.z, v.w);
    if (q == 0) atomicAdd(&g_cnt[b], 1.0f);
}

// ---------------- head MLP ----------------
__global__ void __launch_bounds__(128) k_head(
    const float* __restrict__ Wfc, const float* __restrict__ bfc,
    const float* __restrict__ Wh, const float* __restrict__ bh,
    float* __restrict__ out)
{
    __shared__ float sg[128], sh[128];
    int b = blockIdx.x, t = threadIdx.x;
    float cnt = fmaxf(g_cnt[b], 1.0f);
    sg[t] = g_gsum[(size_t)b * 128 + t] / cnt;
    __syncthreads();
    float a = bfc[t];
#pragma unroll 8
    for (int k = 0; k < 128; k++) a += sg[k] * Wfc[k * 128 + t];
    sh[t] = fmaxf(a, 0.0f);
    __syncthreads();
    if (t < N_HEADSV) {
        float a2 = bh[t];
#pragma unroll 8
        for (int k = 0; k < 128; k++) a2 += sh[k] * Wh[k * 5 + t];
        out[b * 5 + t] = a2;
    }
}

// ---------------- launch ----------------
extern "C" void kernel_launch(void* const* d_in, const int* in_sizes, int n_in,
                              void* d_out, int out_size) {
    (void)in_sizes; (void)n_in; (void)out_size;
    const float* x    = (const float*)d_in[0];
    const float* ea   = (const float*)d_in[1];
    const int*   ei   = (const int*)d_in[2];
    const int*   batch= (const int*)d_in[3];
    const float* W1f  = (const float*)d_in[4];
    const float* b1f  = (const float*)d_in[5];
    const float* W1s  = (const float*)d_in[6];
    const float* b1s  = (const float*)d_in[7];
    const float* Wp   = (const float*)d_in[8];
    const float* bp   = (const float*)d_in[9];
    const float* W2f  = (const float*)d_in[10];
    const float* b2f  = (const float*)d_in[11];
    const float* W2s  = (const float*)d_in[12];
    const float* b2s  = (const float*)d_in[13];
    const float* W3f  = (const float*)d_in[14];
    const float* b3f  = (const float*)d_in[15];
    const float* W3s  = (const float*)d_in[16];
    const float* b3s  = (const float*)d_in[17];
    const float* Wfc  = (const float*)d_in[18];
    const float* bfc  = (const float*)d_in[19];
    const float* Wh   = (const float*)d_in[20];
    const float* bh   = (const float*)d_in[21];
    const int* src = ei;
    const int* dst = ei + N_EDGES;
    float* out = (float*)d_out;

    // 1) init
    k_init<<<(N_NODES * HID + 255) / 256, 256>>>(x);
    // 2) conv1 (channels = 3)
    k_conv1<<<(N_EDGES + 255) / 256, 256>>>(x, ea, src, dst, W1f, b1f, W1s, b1s);
    // 3) node projection 3 -> 128 with relu => g_acc2 (== h2)
    k_nodeproj<<<(N_NODES * HID + 255) / 256, 256>>>(Wp, bp);

    // 4) conv2: node proj table, then fused edge-GEMM + gather/scatter
    k_gemm_node<<<dim3(391, 4), 256>>>(W2f, W2s, 0);
    k_fused<<<N_EDGES / 64, 256>>>(ea, src, dst,
                                   W2f + 256 * 128, W2s + 256 * 128, b2f, b2s, 0);

    // 5) conv3: node proj table (with fused relu + acc3 init), fused edge pass
    k_gemm_node<<<dim3(391, 4), 256>>>(W3f, W3s, 1);
    k_fused<<<N_EDGES / 64, 256>>>(ea, src, dst,
                                   W3f + 256 * 128, W3s + 256 * 128, b3f, b3s, 1);

    // 6) pooling + head
    k_pool<<<(N_NODES * 32 + 255) / 256, 256>>>(batch);
    k_head<<<N_GRAPHS, 128>>>(Wfc, bfc, Wh, bh, out);
}